// round 2
// baseline (speedup 1.0000x reference)
#include <cuda_runtime.h>

#define D_   128
#define ED_  16
#define N_MAX 100000
#define E_MAX 1600000

// scratch: per-node projections p = s_ln @ eW1[0:128], q = s_ln @ eW1[128:256]
__device__ float g_p[(size_t)N_MAX * ED_];
__device__ float g_q[(size_t)N_MAX * ED_];

// One warp per node row: LayerNorm (in/out of s buffer) fused with the two
// 128->16 projections. Lanes 0..15 produce p[row][j], lanes 16..31 q[row][j].
__global__ __launch_bounds__(256) void ln_proj_kernel(
    const float* __restrict__ s_in, float* __restrict__ s_out,
    const float* __restrict__ lnw, const float* __restrict__ lnb,
    const float* __restrict__ eW1 /* layer base, [272*16] row-major */, int n)
{
    __shared__ float sW[4112];        // Wa [2048] | pad 16 | Wb [2048]
    __shared__ float rowbuf[8][D_];
    for (int i = threadIdx.x; i < 2048; i += 256) {
        sW[i]        = eW1[i];        // k in [0,128)
        sW[2064 + i] = eW1[2048 + i]; // k in [128,256)
    }
    __syncthreads();

    int warp = threadIdx.x >> 5, lane = threadIdx.x & 31;
    int row = blockIdx.x * 8 + warp;
    if (row >= n) return;

    float4 v = reinterpret_cast<const float4*>(s_in)[(size_t)row * 32 + lane];
    float ssum = v.x + v.y + v.z + v.w;
    #pragma unroll
    for (int o = 16; o; o >>= 1) ssum += __shfl_xor_sync(0xffffffffu, ssum, o);
    float mu = ssum * 0.0078125f;
    float dx = v.x - mu, dy = v.y - mu, dz = v.z - mu, dw = v.w - mu;
    float sq = dx*dx + dy*dy + dz*dz + dw*dw;
    #pragma unroll
    for (int o = 16; o; o >>= 1) sq += __shfl_xor_sync(0xffffffffu, sq, o);
    float rstd = rsqrtf(sq * 0.0078125f + 1e-5f);

    float4 wv = reinterpret_cast<const float4*>(lnw)[lane];
    float4 bv = reinterpret_cast<const float4*>(lnb)[lane];
    float4 y;
    y.x = dx * rstd * wv.x + bv.x;
    y.y = dy * rstd * wv.y + bv.y;
    y.z = dz * rstd * wv.z + bv.z;
    y.w = dw * rstd * wv.w + bv.w;

    reinterpret_cast<float4*>(s_out)[(size_t)row * 32 + lane] = y;
    reinterpret_cast<float4*>(rowbuf[warp])[lane] = y;
    __syncwarp();

    const float* rb = rowbuf[warp];
    int j = lane & 15;
    const float* W = sW + ((lane < 16) ? 0 : 2064) + j;
    float acc = 0.0f;
    #pragma unroll 8
    for (int k = 0; k < 128; ++k)
        acc = fmaf(rb[k], W[k * 16], acc);

    float* dstp = (lane < 16) ? g_p : g_q;
    dstp[(size_t)row * 16 + j] = acc;
}

// 16 threads per edge: h_j = p[src][j] + q[dst][j] + sum_k ea_k*Wc[k][j] + b1_j
// z = silu(h);  out_j = sum_k z_k*W2[k][j] + b2_j. Matmuls via width-16 shuffles,
// weight columns held in registers (loaded once per thread, reused over the
// grid-stride loop). In-place safe: each group reads/writes only its own edge.
__global__ __launch_bounds__(256) void edge_kernel(
    const int* __restrict__ src, const int* __restrict__ dst,
    const float* __restrict__ ea_in, float* __restrict__ ea_out,
    const float* __restrict__ Wc, const float* __restrict__ b1,
    const float* __restrict__ W2, const float* __restrict__ b2,
    int e_total)
{
    int j = threadIdx.x & 15;
    unsigned gmask = 0xFFFFu << (threadIdx.x & 16);
    float wc[16], w2[16];
    #pragma unroll
    for (int k = 0; k < 16; ++k) { wc[k] = Wc[k * 16 + j]; w2[k] = W2[k * 16 + j]; }
    float b1j = b1[j], b2j = b2[j];

    int group   = (blockIdx.x * 256 + threadIdx.x) >> 4;
    int ngroups = (gridDim.x * 256) >> 4;
    for (int e = group; e < e_total; e += ngroups) {
        int si = src[e];
        int di = dst[e];
        float ea = ea_in[(size_t)e * 16 + j];
        float h = b1j + g_p[(size_t)si * 16 + j] + g_q[(size_t)di * 16 + j];
        #pragma unroll
        for (int k = 0; k < 16; ++k)
            h = fmaf(__shfl_sync(gmask, ea, k, 16), wc[k], h);
        float z = h * (1.0f / (1.0f + __expf(-h)));   // silu
        float o = b2j;
        #pragma unroll
        for (int k = 0; k < 16; ++k)
            o = fmaf(__shfl_sync(gmask, z, k, 16), w2[k], o);
        ea_out[(size_t)e * 16 + j] = o;
    }
}

extern "C" void kernel_launch(void* const* d_in, const int* in_sizes, int n_in,
                              void* d_out, int out_size)
{
    const float* s0   = (const float*)d_in[0];       // [N,128]
    const int*   ei   = (const int*)d_in[1];         // [2,E] int32 (JAX x64 off)
    const float* ea0  = (const float*)d_in[2];       // [E,16]
    // d_in[3] = batch (unused; dead in the reference dataflow)
    const float* lnw  = (const float*)d_in[4];       // [L,128]
    const float* lnb  = (const float*)d_in[5];       // [L,128]
    const float* eW1  = (const float*)d_in[6];       // [L,272,16]
    const float* eb1  = (const float*)d_in[7];       // [L,16]
    const float* eW2  = (const float*)d_in[8];       // [L,16,16]
    const float* eb2  = (const float*)d_in[9];       // [L,16]
    // d_in[10..13] = nW1,nb1,nW2,nb2 : dead (node-MLP output is discarded)

    int n = in_sizes[0] / D_;
    int e = in_sizes[2] / ED_;
    int L = in_sizes[4] / D_;

    float* out    = (float*)d_out;
    float* s_buf  = out;                       // final s lives here
    float* ea_buf = out + (size_t)n * D_;      // final edge_attr lives here

    const int* src = ei;
    const int* dst = ei + e;

    int ln_blocks   = (n + 7) / 8;
    int edge_blocks = 1480;

    for (int i = 0; i < L; ++i) {
        const float* w1_layer = eW1 + (size_t)i * 272 * 16;
        ln_proj_kernel<<<ln_blocks, 256>>>(
            (i == 0) ? s0 : s_buf, s_buf,
            lnw + (size_t)i * D_, lnb + (size_t)i * D_,
            w1_layer, n);
        edge_kernel<<<edge_blocks, 256>>>(
            src, dst,
            (i == 0) ? ea0 : ea_buf, ea_buf,
            w1_layer + 256 * 16, eb1 + (size_t)i * 16,
            eW2 + (size_t)i * 256, eb2 + (size_t)i * 16,
            e);
    }
}

// round 3
// speedup vs baseline: 1.7423x; 1.7423x over previous
#include <cuda_runtime.h>

#define D_   128
#define ED_  16
#define N_MAX 100000

// scratch: per-node projections p = s_ln @ eW1[0:128], q = s_ln @ eW1[128:256]
__device__ float g_p[(size_t)N_MAX * ED_];
__device__ float g_q[(size_t)N_MAX * ED_];

// ---- f32x2 packed helpers (sm_103a FFMA2 path) ----
__device__ __forceinline__ unsigned long long pk2(float a) {
    unsigned long long r;
    asm("mov.b64 %0, {%1, %1};" : "=l"(r) : "f"(a));
    return r;
}
__device__ __forceinline__ unsigned long long pack2(float a, float b) {
    unsigned long long r;
    asm("mov.b64 %0, {%1, %2};" : "=l"(r) : "f"(a), "f"(b));
    return r;
}
__device__ __forceinline__ float2 up2(unsigned long long v) {
    float2 r;
    asm("mov.b64 {%0, %1}, %2;" : "=f"(r.x), "=f"(r.y) : "l"(v));
    return r;
}
__device__ __forceinline__ unsigned long long fma2(unsigned long long a,
                                                   unsigned long long b,
                                                   unsigned long long c) {
    unsigned long long d;
    asm("fma.rn.f32x2 %0, %1, %2, %3;" : "=l"(d) : "l"(a), "l"(b), "l"(c));
    return d;
}
__device__ __forceinline__ unsigned long long add2(unsigned long long a,
                                                   unsigned long long b) {
    unsigned long long d;
    asm("add.rn.f32x2 %0, %1, %2;" : "=l"(d) : "l"(a), "l"(b));
    return d;
}

// Persistent blocks; weights transposed into smem ONCE per block.
// One warp per row per iteration: LayerNorm fused with the two 128->16
// projections (lanes 0..15 -> p[row][j], lanes 16..31 -> q[row][j]),
// projection via f32x2 over a conflict-free transposed weight layout.
__global__ __launch_bounds__(256) void ln_proj_kernel(
    const float* __restrict__ s_in, float* __restrict__ s_out,
    const float* __restrict__ lnw, const float* __restrict__ lnb,
    const float* __restrict__ eW1 /* [272,16] row-major */, int n)
{
    // wT rows 0-15: Wa^T[j][k] (k=0..127), rows 16-31: Wb^T[j][k]; stride 132
    __shared__ __align__(16) float wT[32 * 132];
    __shared__ __align__(16) float rowbuf[8][D_];

    for (int idx = threadIdx.x; idx < 2048; idx += 256) {
        int k = idx >> 4, j = idx & 15;
        wT[j * 132 + k]        = eW1[idx];          // Wa: k in [0,128)
        wT[(16 + j) * 132 + k] = eW1[2048 + idx];   // Wb: k in [128,256)
    }
    __syncthreads();

    int warp = threadIdx.x >> 5, lane = threadIdx.x & 31;
    float4 wv = reinterpret_cast<const float4*>(lnw)[lane];
    float4 bv = reinterpret_cast<const float4*>(lnb)[lane];
    const ulonglong2* wrow2 =
        reinterpret_cast<const ulonglong2*>(wT + lane * 132);
    const ulonglong2* rbv =
        reinterpret_cast<const ulonglong2*>(rowbuf[warp]);
    float* dstp = (lane < 16) ? (g_p + (lane & 15)) : (g_q + (lane & 15));

    for (int row = blockIdx.x * 8 + warp; row < n; row += gridDim.x * 8) {
        float4 v = reinterpret_cast<const float4*>(s_in)[(size_t)row * 32 + lane];
        float ssum = v.x + v.y + v.z + v.w;
        #pragma unroll
        for (int o = 16; o; o >>= 1) ssum += __shfl_xor_sync(0xffffffffu, ssum, o);
        float mu = ssum * 0.0078125f;
        float dx = v.x - mu, dy = v.y - mu, dz = v.z - mu, dw = v.w - mu;
        float sq = dx*dx + dy*dy + dz*dz + dw*dw;
        #pragma unroll
        for (int o = 16; o; o >>= 1) sq += __shfl_xor_sync(0xffffffffu, sq, o);
        float rstd = rsqrtf(sq * 0.0078125f + 1e-5f);

        float4 y;
        y.x = dx * rstd * wv.x + bv.x;
        y.y = dy * rstd * wv.y + bv.y;
        y.z = dz * rstd * wv.z + bv.z;
        y.w = dw * rstd * wv.w + bv.w;

        reinterpret_cast<float4*>(s_out)[(size_t)row * 32 + lane] = y;
        reinterpret_cast<float4*>(rowbuf[warp])[lane] = y;
        __syncwarp();

        unsigned long long acc0 = 0ull, acc1 = 0ull;
        #pragma unroll
        for (int c = 0; c < 32; ++c) {
            ulonglong2 w2 = wrow2[c];
            ulonglong2 r2 = rbv[c];
            acc0 = fma2(r2.x, w2.x, acc0);
            acc1 = fma2(r2.y, w2.y, acc1);
        }
        float2 a0 = up2(acc0), a1 = up2(acc1);
        dstp[(size_t)row * 16] = a0.x + a0.y + a1.x + a1.y;
        __syncwarp();
    }
}

// One thread per edge. Weights in smem (broadcast LDS.128), all math in
// packed f32x2: 8 independent accumulators per matmul -> high ILP, no shuffles.
__global__ __launch_bounds__(256) void edge_kernel(
    const int* __restrict__ src, const int* __restrict__ dst,
    const float* __restrict__ ea_in, float* __restrict__ ea_out,
    const float* __restrict__ Wc, const float* __restrict__ b1,
    const float* __restrict__ W2, const float* __restrict__ b2,
    int e_total)
{
    __shared__ __align__(16) float sWc[256], sW2[256];
    __shared__ unsigned long long sB1[8], sB2[8];
    sWc[threadIdx.x] = Wc[threadIdx.x];
    sW2[threadIdx.x] = W2[threadIdx.x];
    if (threadIdx.x < 8) {
        sB1[threadIdx.x] = pack2(b1[2*threadIdx.x], b1[2*threadIdx.x + 1]);
        sB2[threadIdx.x] = pack2(b2[2*threadIdx.x], b2[2*threadIdx.x + 1]);
    }
    __syncthreads();

    int e = blockIdx.x * 256 + threadIdx.x;
    if (e >= e_total) return;

    int si = src[e], di = dst[e];
    const ulonglong2* P = reinterpret_cast<const ulonglong2*>(g_p + (size_t)si * 16);
    const ulonglong2* Q = reinterpret_cast<const ulonglong2*>(g_q + (size_t)di * 16);

    unsigned long long h[8];
    #pragma unroll
    for (int i = 0; i < 4; ++i) {
        ulonglong2 pv = P[i], qv = Q[i];
        h[2*i+0] = add2(add2(pv.x, qv.x), sB1[2*i+0]);
        h[2*i+1] = add2(add2(pv.y, qv.y), sB1[2*i+1]);
    }

    const ulonglong2* WC = reinterpret_cast<const ulonglong2*>(sWc);
    const float4* EA = reinterpret_cast<const float4*>(ea_in + (size_t)e * 16);
    #pragma unroll
    for (int c = 0; c < 4; ++c) {
        float4 ev = EA[c];
        float es[4] = {ev.x, ev.y, ev.z, ev.w};
        #pragma unroll
        for (int kk = 0; kk < 4; ++kk) {
            int k = c * 4 + kk;
            unsigned long long ek = pk2(es[kk]);
            ulonglong2 w0 = WC[k*4+0], w1 = WC[k*4+1];
            ulonglong2 w2v = WC[k*4+2], w3 = WC[k*4+3];
            h[0] = fma2(ek, w0.x,  h[0]);  h[1] = fma2(ek, w0.y,  h[1]);
            h[2] = fma2(ek, w1.x,  h[2]);  h[3] = fma2(ek, w1.y,  h[3]);
            h[4] = fma2(ek, w2v.x, h[4]);  h[5] = fma2(ek, w2v.y, h[5]);
            h[6] = fma2(ek, w3.x,  h[6]);  h[7] = fma2(ek, w3.y,  h[7]);
        }
    }

    float z[16];
    #pragma unroll
    for (int i = 0; i < 8; ++i) {
        float2 hv = up2(h[i]);
        z[2*i]   = __fdividef(hv.x, 1.0f + __expf(-hv.x));   // silu
        z[2*i+1] = __fdividef(hv.y, 1.0f + __expf(-hv.y));
    }

    unsigned long long o[8];
    #pragma unroll
    for (int i = 0; i < 8; ++i) o[i] = sB2[i];
    const ulonglong2* WT = reinterpret_cast<const ulonglong2*>(sW2);
    #pragma unroll
    for (int k = 0; k < 16; ++k) {
        unsigned long long zk = pk2(z[k]);
        ulonglong2 w0 = WT[k*4+0], w1 = WT[k*4+1];
        ulonglong2 w2v = WT[k*4+2], w3 = WT[k*4+3];
        o[0] = fma2(zk, w0.x,  o[0]);  o[1] = fma2(zk, w0.y,  o[1]);
        o[2] = fma2(zk, w1.x,  o[2]);  o[3] = fma2(zk, w1.y,  o[3]);
        o[4] = fma2(zk, w2v.x, o[4]);  o[5] = fma2(zk, w2v.y, o[5]);
        o[6] = fma2(zk, w3.x,  o[6]);  o[7] = fma2(zk, w3.y,  o[7]);
    }

    ulonglong2* OUT = reinterpret_cast<ulonglong2*>(ea_out + (size_t)e * 16);
    #pragma unroll
    for (int i = 0; i < 4; ++i)
        OUT[i] = make_ulonglong2(o[2*i], o[2*i+1]);
}

extern "C" void kernel_launch(void* const* d_in, const int* in_sizes, int n_in,
                              void* d_out, int out_size)
{
    const float* s0   = (const float*)d_in[0];       // [N,128]
    const int*   ei   = (const int*)d_in[1];         // [2,E] int32
    const float* ea0  = (const float*)d_in[2];       // [E,16]
    const float* lnw  = (const float*)d_in[4];       // [L,128]
    const float* lnb  = (const float*)d_in[5];       // [L,128]
    const float* eW1  = (const float*)d_in[6];       // [L,272,16]
    const float* eb1  = (const float*)d_in[7];       // [L,16]
    const float* eW2  = (const float*)d_in[8];       // [L,16,16]
    const float* eb2  = (const float*)d_in[9];       // [L,16]
    // batch / nW1 / nb1 / nW2 / nb2 are dead in the reference dataflow

    int n = in_sizes[0] / D_;
    int e = in_sizes[2] / ED_;
    int L = in_sizes[4] / D_;

    float* out    = (float*)d_out;
    float* s_buf  = out;                      // final s
    float* ea_buf = out + (size_t)n * D_;     // final edge_attr

    const int* src = ei;
    const int* dst = ei + e;

    int ln_blocks   = 296;                    // persistent, 2 blocks/SM
    int edge_blocks = (e + 255) / 256;

    for (int i = 0; i < L; ++i) {
        const float* w1_layer = eW1 + (size_t)i * 272 * 16;
        ln_proj_kernel<<<ln_blocks, 256>>>(
            (i == 0) ? s0 : s_buf, s_buf,
            lnw + (size_t)i * D_, lnb + (size_t)i * D_,
            w1_layer, n);
        edge_kernel<<<edge_blocks, 256>>>(
            src, dst,
            (i == 0) ? ea0 : ea_buf, ea_buf,
            w1_layer + 256 * 16, eb1 + (size_t)i * 16,
            eW2 + (size_t)i * 256, eb2 + (size_t)i * 16,
            e);
    }
}

// round 4
// speedup vs baseline: 2.3564x; 1.3525x over previous
#include <cuda_runtime.h>

#define D_    128
#define ED_   16
#define N_MAX 100000
#define L_MAX 5

// per-layer per-node projections: p[l][n][j] = s_ln_l[n] @ Wa_l ; q = @ Wb_l
__device__ float g_p[(size_t)L_MAX * N_MAX * ED_];
__device__ float g_q[(size_t)L_MAX * N_MAX * ED_];

// edge-MLP weights, bit-packed as float pairs for fma.rn.f32x2
__constant__ __align__(16) ulonglong2 cWC[L_MAX][64];          // eW1 rows 256..271 (edge_attr part)
__constant__ __align__(16) ulonglong2 cW2[L_MAX][64];          // eW2
__constant__ __align__(16) unsigned long long cB1[L_MAX][8];   // eb1
__constant__ __align__(16) unsigned long long cB2[L_MAX][8];   // eb2

// ---- f32x2 packed helpers ----
__device__ __forceinline__ unsigned long long pk2(float a) {
    unsigned long long r; asm("mov.b64 %0, {%1, %1};" : "=l"(r) : "f"(a)); return r;
}
__device__ __forceinline__ float2 up2(unsigned long long v) {
    float2 r; asm("mov.b64 {%0, %1}, %2;" : "=f"(r.x), "=f"(r.y) : "l"(v)); return r;
}
__device__ __forceinline__ unsigned long long fma2(unsigned long long a,
                                                   unsigned long long b,
                                                   unsigned long long c) {
    unsigned long long d;
    asm("fma.rn.f32x2 %0, %1, %2, %3;" : "=l"(d) : "l"(a), "l"(b), "l"(c));
    return d;
}
__device__ __forceinline__ unsigned long long add2(unsigned long long a,
                                                   unsigned long long b) {
    unsigned long long d;
    asm("add.rn.f32x2 %0, %1, %2;" : "=l"(d) : "l"(a), "l"(b));
    return d;
}

// ---------------------------------------------------------------------------
// ALL 5 layers of LayerNorm + the two 128->16 projections in one pass.
// Row lives in registers across layers; weights for all layers in dyn smem.
// One warp per row. Lanes 0..15 -> p[l][row][j], lanes 16..31 -> q[l][row][j].
// ---------------------------------------------------------------------------
__global__ __launch_bounds__(256) void ln_all_kernel(
    const float* __restrict__ s_in, float* __restrict__ s_out,
    const float* __restrict__ lnw, const float* __restrict__ lnb,
    const float* __restrict__ eW1 /* [L,272,16] */, int n, int L)
{
    extern __shared__ __align__(16) float smem_dyn[];
    float* wT  = smem_dyn;                 // [L][32*132] transposed Wa|Wb
    float* sLn = wT + L_MAX * 4224;        // [L][256] = lnw | lnb
    float* rowbuf = sLn + L_MAX * 256;     // [8][128]

    for (int l = 0; l < L; ++l) {
        const float* w1 = eW1 + (size_t)l * 272 * 16;
        float* wTl = wT + l * 4224;
        for (int idx = threadIdx.x; idx < 2048; idx += 256) {
            int k = idx >> 4, j = idx & 15;
            wTl[j * 132 + k]        = w1[idx];          // Wa: k in [0,128)
            wTl[(16 + j) * 132 + k] = w1[2048 + idx];   // Wb: k in [128,256)
        }
        for (int idx = threadIdx.x; idx < 128; idx += 256) {
            sLn[l * 256 + idx]       = lnw[l * 128 + idx];
            sLn[l * 256 + 128 + idx] = lnb[l * 128 + idx];
        }
    }
    __syncthreads();

    int warp = threadIdx.x >> 5, lane = threadIdx.x & 31;
    float* rb = rowbuf + warp * 128;
    int j = lane & 15;
    int rowsel = (lane < 16) ? 0 : 16;
    float* dstbase = (lane < 16) ? g_p : g_q;

    for (int row = blockIdx.x * 8 + warp; row < n; row += gridDim.x * 8) {
        float4 v = reinterpret_cast<const float4*>(s_in)[(size_t)row * 32 + lane];

        for (int l = 0; l < L; ++l) {
            // joint mean / mean-square reduction (two independent shfl chains)
            float s1 = (v.x + v.y) + (v.z + v.w);
            float s2 = fmaf(v.x, v.x, fmaf(v.y, v.y, fmaf(v.z, v.z, v.w * v.w)));
            #pragma unroll
            for (int o = 16; o; o >>= 1) {
                s1 += __shfl_xor_sync(0xffffffffu, s1, o);
                s2 += __shfl_xor_sync(0xffffffffu, s2, o);
            }
            float mu  = s1 * 0.0078125f;
            float var = fmaf(s2, 0.0078125f, -mu * mu);
            float rstd = rsqrtf(var + 1e-5f);

            float4 wv = reinterpret_cast<const float4*>(sLn + l * 256)[lane];
            float4 bv = reinterpret_cast<const float4*>(sLn + l * 256 + 128)[lane];
            v.x = (v.x - mu) * rstd * wv.x + bv.x;
            v.y = (v.y - mu) * rstd * wv.y + bv.y;
            v.z = (v.z - mu) * rstd * wv.z + bv.z;
            v.w = (v.w - mu) * rstd * wv.w + bv.w;

            reinterpret_cast<float4*>(rb)[lane] = v;
            __syncwarp();

            const ulonglong2* wrow =
                reinterpret_cast<const ulonglong2*>(wT + l * 4224 + (rowsel + j) * 132);
            const ulonglong2* rv = reinterpret_cast<const ulonglong2*>(rb);
            unsigned long long a0 = 0ull, a1 = 0ull, a2 = 0ull, a3 = 0ull;
            #pragma unroll
            for (int c = 0; c < 32; c += 2) {
                ulonglong2 w0 = wrow[c], w1v = wrow[c + 1];
                ulonglong2 r0 = rv[c],   r1  = rv[c + 1];
                a0 = fma2(r0.x, w0.x,  a0);
                a1 = fma2(r0.y, w0.y,  a1);
                a2 = fma2(r1.x, w1v.x, a2);
                a3 = fma2(r1.y, w1v.y, a3);
            }
            float2 f0 = up2(a0), f1 = up2(a1), f2 = up2(a2), f3 = up2(a3);
            float dot = ((f0.x + f0.y) + (f1.x + f1.y)) +
                        ((f2.x + f2.y) + (f3.x + f3.y));
            dstbase[((size_t)l * N_MAX + row) * 16 + j] = dot;
            __syncwarp();
        }
        reinterpret_cast<float4*>(s_out)[(size_t)row * 32 + lane] = v;
    }
}

// ---------------------------------------------------------------------------
// One thread per edge; weights via constant port (no L1/shared traffic),
// all math in packed f32x2 with 8 independent accumulators.
// ---------------------------------------------------------------------------
__global__ __launch_bounds__(256) void edge_kernel(
    const int* __restrict__ src, const int* __restrict__ dst,
    const float* __restrict__ ea_in, float* __restrict__ ea_out,
    int layer, int e_total)
{
    int e = blockIdx.x * 256 + threadIdx.x;
    if (e >= e_total) return;

    int si = src[e], di = dst[e];
    const ulonglong2* P =
        reinterpret_cast<const ulonglong2*>(g_p + ((size_t)layer * N_MAX + si) * 16);
    const ulonglong2* Q =
        reinterpret_cast<const ulonglong2*>(g_q + ((size_t)layer * N_MAX + di) * 16);

    unsigned long long h[8];
    #pragma unroll
    for (int i = 0; i < 4; ++i) {
        ulonglong2 pv = P[i], qv = Q[i];
        h[2*i+0] = add2(add2(pv.x, qv.x), cB1[layer][2*i+0]);
        h[2*i+1] = add2(add2(pv.y, qv.y), cB1[layer][2*i+1]);
    }

    const float4* EA = reinterpret_cast<const float4*>(ea_in + (size_t)e * 16);
    #pragma unroll
    for (int c = 0; c < 4; ++c) {
        float4 ev = EA[c];
        float es[4] = {ev.x, ev.y, ev.z, ev.w};
        #pragma unroll
        for (int kk = 0; kk < 4; ++kk) {
            int k = c * 4 + kk;
            unsigned long long ek = pk2(es[kk]);
            ulonglong2 w0 = cWC[layer][k*4+0], w1 = cWC[layer][k*4+1];
            ulonglong2 w2v = cWC[layer][k*4+2], w3 = cWC[layer][k*4+3];
            h[0] = fma2(ek, w0.x,  h[0]);  h[1] = fma2(ek, w0.y,  h[1]);
            h[2] = fma2(ek, w1.x,  h[2]);  h[3] = fma2(ek, w1.y,  h[3]);
            h[4] = fma2(ek, w2v.x, h[4]);  h[5] = fma2(ek, w2v.y, h[5]);
            h[6] = fma2(ek, w3.x,  h[6]);  h[7] = fma2(ek, w3.y,  h[7]);
        }
    }

    float z[16];
    #pragma unroll
    for (int i = 0; i < 8; ++i) {
        float2 hv = up2(h[i]);
        z[2*i]   = __fdividef(hv.x, 1.0f + __expf(-hv.x));   // silu
        z[2*i+1] = __fdividef(hv.y, 1.0f + __expf(-hv.y));
    }

    unsigned long long o[8];
    #pragma unroll
    for (int i = 0; i < 8; ++i) o[i] = cB2[layer][i];
    #pragma unroll
    for (int k = 0; k < 16; ++k) {
        unsigned long long zk = pk2(z[k]);
        ulonglong2 w0 = cW2[layer][k*4+0], w1 = cW2[layer][k*4+1];
        ulonglong2 w2v = cW2[layer][k*4+2], w3 = cW2[layer][k*4+3];
        o[0] = fma2(zk, w0.x,  o[0]);  o[1] = fma2(zk, w0.y,  o[1]);
        o[2] = fma2(zk, w1.x,  o[2]);  o[3] = fma2(zk, w1.y,  o[3]);
        o[4] = fma2(zk, w2v.x, o[4]);  o[5] = fma2(zk, w2v.y, o[5]);
        o[6] = fma2(zk, w3.x,  o[6]);  o[7] = fma2(zk, w3.y,  o[7]);
    }

    ulonglong2* OUT = reinterpret_cast<ulonglong2*>(ea_out + (size_t)e * 16);
    #pragma unroll
    for (int i = 0; i < 4; ++i)
        OUT[i] = make_ulonglong2(o[2*i], o[2*i+1]);
}

extern "C" void kernel_launch(void* const* d_in, const int* in_sizes, int n_in,
                              void* d_out, int out_size)
{
    const float* s0   = (const float*)d_in[0];       // [N,128]
    const int*   ei   = (const int*)d_in[1];         // [2,E] int32
    const float* ea0  = (const float*)d_in[2];       // [E,16]
    const float* lnw  = (const float*)d_in[4];       // [L,128]
    const float* lnb  = (const float*)d_in[5];       // [L,128]
    const float* eW1  = (const float*)d_in[6];       // [L,272,16]
    const float* eb1  = (const float*)d_in[7];       // [L,16]
    const float* eW2  = (const float*)d_in[8];       // [L,16,16]
    const float* eb2  = (const float*)d_in[9];       // [L,16]
    // batch / nW1 / nb1 / nW2 / nb2 are dead in the reference dataflow

    int n = in_sizes[0] / D_;
    int e = in_sizes[2] / ED_;
    int L = in_sizes[4] / D_;

    float* out    = (float*)d_out;
    float* s_buf  = out;                      // final s
    float* ea_buf = out + (size_t)n * D_;     // final edge_attr

    const int* src = ei;
    const int* dst = ei + e;

    // stage edge-MLP weights into constant memory (capturable D2D copies)
    void *pWC, *pW2, *pB1, *pB2;
    cudaGetSymbolAddress(&pWC, cWC);
    cudaGetSymbolAddress(&pW2, cW2);
    cudaGetSymbolAddress(&pB1, cB1);
    cudaGetSymbolAddress(&pB2, cB2);
    cudaMemcpy2DAsync(pWC, 1024, eW1 + 256 * 16, 272 * 16 * 4, 1024, L,
                      cudaMemcpyDeviceToDevice);
    cudaMemcpyAsync(pW2, eW2, (size_t)L * 256 * 4, cudaMemcpyDeviceToDevice);
    cudaMemcpyAsync(pB1, eb1, (size_t)L * 16 * 4, cudaMemcpyDeviceToDevice);
    cudaMemcpyAsync(pB2, eb2, (size_t)L * 16 * 4, cudaMemcpyDeviceToDevice);

    size_t shmem = (size_t)(L_MAX * 4224 + L_MAX * 256 + 8 * 128) * 4;
    cudaFuncSetAttribute(ln_all_kernel,
                         cudaFuncAttributeMaxDynamicSharedMemorySize, (int)shmem);

    ln_all_kernel<<<296, 256, shmem>>>(s0, s_buf, lnw, lnb, eW1, n, L);

    int edge_blocks = (e + 255) / 256;
    for (int i = 0; i < L; ++i) {
        edge_kernel<<<edge_blocks, 256>>>(
            src, dst,
            (i == 0) ? ea0 : ea_buf, ea_buf,
            i, e);
    }
}